// round 8
// baseline (speedup 1.0000x reference)
#include <cuda_runtime.h>
#include <cuda_bf16.h>
#include <math.h>
#include <stdint.h>

// ---------------------------------------------------------------------------
// Problem constants
// ---------------------------------------------------------------------------
#define N_TOK   8192
#define DIM     1024
#define VOCAB   50257
#define IGNORE  (-100)

// GEMM tiling (bf16: 128-byte SMEM rows = 64 k-elements)
#define BM 128
#define BN 256
#define BKE 64                              // k elements per stage
#define NSTAGES 3
#define NSLICES 37                          // 64*37 = 2368 = 16 waves of 148
#define NTILES  ((VOCAB + BN - 1) / BN)     // 197
#define KCHUNKS (DIM / BKE)                 // 16
#define NPART   (NSLICES * 4)               // 148 (4 n-warps per slice)

#define STAGE_A_BYTES (BM * BKE * 2)        // 16 KB
#define STAGE_B_BYTES (BN * BKE * 2)        // 32 KB
#define STAGE_BYTES   (STAGE_A_BYTES + STAGE_B_BYTES)
#define SMEM_BYTES    (NSTAGES * STAGE_BYTES)   // 144 KB

#define NEG_INF __int_as_float(0xff800000)

// ---------------------------------------------------------------------------
// Device scratch (allocation-free)
// ---------------------------------------------------------------------------
__device__ __align__(16) __nv_bfloat16 g_e16[N_TOK * DIM];
__device__ __align__(16) __nv_bfloat16 g_c16[VOCAB * DIM];
__device__ float g_pm[NPART * N_TOK];
__device__ float g_ps[NPART * N_TOK];
__device__ float g_nll[N_TOK];

// ---------------------------------------------------------------------------
// PTX helpers (baseline ISA only — compiles under compute_103 non-'a')
// ---------------------------------------------------------------------------
__device__ __forceinline__ uint32_t smem_u32(const void* p) {
    uint32_t a;
    asm("{ .reg .u64 t; cvta.to.shared.u64 t, %1; cvt.u32.u64 %0, t; }" : "=r"(a) : "l"(p));
    return a;
}
__device__ __forceinline__ void cp_async16(uint32_t dst, const void* src, int sz) {
    asm volatile("cp.async.cg.shared.global [%0], [%1], 16, %2;"
                 :: "r"(dst), "l"(src), "r"(sz));
}
__device__ __forceinline__ void ldsm4(uint32_t& r0, uint32_t& r1, uint32_t& r2,
                                      uint32_t& r3, uint32_t addr) {
    asm volatile("ldmatrix.sync.aligned.m8n8.x4.shared.b16 {%0,%1,%2,%3}, [%4];"
                 : "=r"(r0), "=r"(r1), "=r"(r2), "=r"(r3) : "r"(addr));
}
__device__ __forceinline__ void mma_bf16(float* c, const uint32_t* a, const uint32_t* b) {
    asm volatile(
        "mma.sync.aligned.m16n8k16.row.col.f32.bf16.bf16.f32 "
        "{%0,%1,%2,%3}, {%4,%5,%6,%7}, {%8,%9}, {%0,%1,%2,%3};"
        : "+f"(c[0]), "+f"(c[1]), "+f"(c[2]), "+f"(c[3])
        : "r"(a[0]), "r"(a[1]), "r"(a[2]), "r"(a[3]), "r"(b[0]), "r"(b[1]));
}

// ---------------------------------------------------------------------------
// Pre-pass: fp32 -> bf16 round-to-nearest. 8 elements / thread.
// ---------------------------------------------------------------------------
__global__ void k_cvt(const float4* __restrict__ in, uint4* __restrict__ out, int n8) {
    int i = blockIdx.x * blockDim.x + threadIdx.x;
    if (i < n8) {
        float4 v0 = in[2 * i];
        float4 v1 = in[2 * i + 1];
        __nv_bfloat162 b0 = __float22bfloat162_rn(make_float2(v0.x, v0.y));
        __nv_bfloat162 b1 = __float22bfloat162_rn(make_float2(v0.z, v0.w));
        __nv_bfloat162 b2 = __float22bfloat162_rn(make_float2(v1.x, v1.y));
        __nv_bfloat162 b3 = __float22bfloat162_rn(make_float2(v1.z, v1.w));
        uint4 o;
        o.x = *(uint32_t*)&b0; o.y = *(uint32_t*)&b1;
        o.z = *(uint32_t*)&b2; o.w = *(uint32_t*)&b3;
        out[i] = o;
    }
}

// ---------------------------------------------------------------------------
// Main fused GEMM (mma.sync bf16 m16n8k16) + online logsumexp.
// CTA tile 128x256, 256 threads = 8 warps in 2(m) x 4(n) grid; 64x64 warp
// tiles (4 m16 x 8 n8 per warp). Grid (64 row-tiles, 37 slices); slice s owns
// vocab tiles {s, s+37, s+74, ...}. 1 CTA/SM (144 KB smem, ~200 regs).
// ---------------------------------------------------------------------------
__global__ void __launch_bounds__(256, 1)
k_cce(const __nv_bfloat16* __restrict__ ge, const __nv_bfloat16* __restrict__ gc)
{
    extern __shared__ char smem[];
    const uint32_t sb = smem_u32(smem);
    const int tid  = threadIdx.x;
    const int lane = tid & 31;
    const int wid  = tid >> 5;
    const int warp_m = wid & 1;
    const int warp_n = wid >> 1;
    const int row0  = blockIdx.x * BM;
    const int slice = blockIdx.y;
    const int ntiles = (NTILES - slice + NSLICES - 1) / NSLICES;
    const int S = ntiles * KCHUNKS;

    // cp.async per-thread layout (128B rows, XOR-16B swizzle):
    // A: 128 rows x 8 chunks = 4 iters; B: 256 rows x 8 chunks = 8 iters.
    const int ar = tid >> 3;
    const int ac = tid & 7;
    const uint32_t st_off = ar * 128 + ((ac ^ (ar & 7)) << 4);
    const __nv_bfloat16* gA0 = ge + (size_t)(row0 + ar) * DIM + ac * 8;

    // ldmatrix addressing
    const int rA = warp_m * 64 + (lane & 15);
    uint32_t aoff[4];
#pragma unroll
    for (int mt = 0; mt < 4; mt++) aoff[mt] = (rA + mt * 16) * 128;
    const uint32_t asw = rA & 7;                      // mt*16 preserves row&7
    const int ahi = lane >> 4;
    const int rB  = ((lane >> 4) << 3) + (lane & 7);
    uint32_t boff[4];
#pragma unroll
    for (int p = 0; p < 4; p++) boff[p] = (warp_n * 64 + p * 16 + rB) * 128;
    const uint32_t bsw = lane & 7;
    const int bhi = (lane >> 3) & 1;

    // ---- stage loader ----
    auto load_stage = [&](int s, int buf) {
        const int kc   = s & (KCHUNKS - 1);
        const int tix  = slice + (s >> 4) * NSLICES;
        const int col0 = tix * BN;
        const uint32_t as = sb + buf * STAGE_BYTES;
        const uint32_t bs = as + STAGE_A_BYTES;
        const __nv_bfloat16* ga = gA0 + kc * BKE;
#pragma unroll
        for (int i = 0; i < 4; i++)
            cp_async16(as + st_off + i * 4096, ga + (size_t)i * 32 * DIM, 16);
        const int vr0 = col0 + ar;
#pragma unroll
        for (int i = 0; i < 8; i++) {
            int vr = vr0 + i * 32;
            int ok = vr < VOCAB;
            const __nv_bfloat16* gb = gc + (size_t)(ok ? vr : 0) * DIM + kc * BKE + ac * 8;
            cp_async16(bs + st_off + i * 4096, gb, ok ? 16 : 0);  // sz=0 zero-fills
        }
    };

    // ---- pipeline prologue ----
    int s_issue = 0, buf_issue = 0;
#pragma unroll
    for (int i = 0; i < NSTAGES - 1; i++) {
        load_stage(s_issue, buf_issue);
        asm volatile("cp.async.commit_group;" ::: "memory");
        s_issue++;
        buf_issue = (buf_issue == NSTAGES - 1) ? 0 : buf_issue + 1;
    }

    float msta[8], ssta[8];
#pragma unroll
    for (int i = 0; i < 8; i++) { msta[i] = NEG_INF; ssta[i] = 0.0f; }

    int buf_c = 0;
    for (int tt = 0; tt < ntiles; tt++) {
        const int tix  = slice + tt * NSLICES;
        const int col0 = tix * BN;
        const bool boundary = (tix == NTILES - 1);

        float acc[4][8][4];
#pragma unroll
        for (int mt = 0; mt < 4; mt++)
#pragma unroll
            for (int nt = 0; nt < 8; nt++)
#pragma unroll
                for (int k = 0; k < 4; k++) acc[mt][nt][k] = 0.0f;

#pragma unroll 1
        for (int kc = 0; kc < KCHUNKS; kc++) {
            asm volatile("cp.async.wait_group 1;" ::: "memory");
            __syncthreads();
            if (s_issue < S) load_stage(s_issue, buf_issue);
            asm volatile("cp.async.commit_group;" ::: "memory");
            s_issue++;
            buf_issue = (buf_issue == NSTAGES - 1) ? 0 : buf_issue + 1;

            const uint32_t as = sb + buf_c * STAGE_BYTES;
            const uint32_t bs = as + STAGE_A_BYTES;
#pragma unroll
            for (int ks = 0; ks < 4; ks++) {      // 4 x k16 per 64-elt chunk
                uint32_t af[4][4], bf[8][2];
                const uint32_t ach = (uint32_t)(2 * ks + ahi);
#pragma unroll
                for (int mt = 0; mt < 4; mt++)
                    ldsm4(af[mt][0], af[mt][1], af[mt][2], af[mt][3],
                          as + aoff[mt] + ((ach ^ asw) << 4));
                const uint32_t bch = (uint32_t)(2 * ks + bhi);
#pragma unroll
                for (int p = 0; p < 4; p++)
                    ldsm4(bf[2 * p][0], bf[2 * p][1], bf[2 * p + 1][0], bf[2 * p + 1][1],
                          bs + boff[p] + ((bch ^ bsw) << 4));
#pragma unroll
                for (int mt = 0; mt < 4; mt++)
#pragma unroll
                    for (int nt = 0; nt < 8; nt++)
                        mma_bf16(acc[mt][nt], af[mt], bf[nt]);
            }
            buf_c = (buf_c == NSTAGES - 1) ? 0 : buf_c + 1;
        }

        // ---- fused online-logsumexp epilogue on register fragments ----
        const int colt = col0 + warp_n * 64 + 2 * (lane & 3);
#pragma unroll
        for (int mt = 0; mt < 4; mt++) {
#pragma unroll
            for (int h = 0; h < 2; h++) {
                const int rg = mt * 2 + h;
                float tmax = NEG_INF;
#pragma unroll
                for (int nt = 0; nt < 8; nt++)
#pragma unroll
                    for (int j = 0; j < 2; j++) {
                        float v = acc[mt][nt][h * 2 + j];
                        if (boundary && (colt + nt * 8 + j) >= VOCAB) v = NEG_INF;
                        tmax = fmaxf(tmax, v);
                    }
                const float nm = fmaxf(msta[rg], tmax);
                float add = 0.0f;
#pragma unroll
                for (int nt = 0; nt < 8; nt++)
#pragma unroll
                    for (int j = 0; j < 2; j++) {
                        float v = acc[mt][nt][h * 2 + j];
                        if (boundary && (colt + nt * 8 + j) >= VOCAB) v = NEG_INF;
                        add += __expf(v - nm);
                    }
                ssta[rg] = ssta[rg] * __expf(msta[rg] - nm) + add;
                msta[rg] = nm;
            }
        }
    }
    asm volatile("cp.async.wait_group 0;" ::: "memory");

    // ---- merge the 4 lanes of each quad; store per (slice, warp_n) ----
#pragma unroll
    for (int rg = 0; rg < 8; rg++) {
        float m = msta[rg], s = ssta[rg];
#pragma unroll
        for (int off = 1; off <= 2; off <<= 1) {
            float om = __shfl_xor_sync(0xffffffffu, m, off);
            float os = __shfl_xor_sync(0xffffffffu, s, off);
            float nm = fmaxf(m, om);
            s = s * __expf(m - nm) + os * __expf(om - nm);
            m = nm;
        }
        if ((lane & 3) == 0) {
            const int row = row0 + warp_m * 64 + (rg >> 1) * 16 + (rg & 1) * 8 + (lane >> 2);
            const int p = slice * 4 + warp_n;
            g_pm[p * N_TOK + row] = m;
            g_ps[p * N_TOK + row] = s;
        }
    }
}

// ---------------------------------------------------------------------------
// Target dtype sniffing (int64 vs int32)
// ---------------------------------------------------------------------------
__device__ __forceinline__ bool targets_are_i64(const int* t32) {
#pragma unroll
    for (int j = 1; j < 64; j += 2) {
        int w = t32[j];
        if (w != 0 && w != -1) return false;
    }
    return true;
}
__device__ __forceinline__ long long get_target(const void* tp, int row, bool is64) {
    if (is64) return ((const long long*)tp)[row];
    return (long long)((const int*)tp)[row];
}

// ---------------------------------------------------------------------------
// Kernel 2: merge 148 partials -> lse (warp-parallel); exact fp32 target dot
// (float4-vectorized); nll[row].
// ---------------------------------------------------------------------------
__global__ __launch_bounds__(128)
void k_row_nll(const float* __restrict__ e, const float* __restrict__ c,
               const void* __restrict__ targets)
{
    const int row = blockIdx.x;
    __shared__ float sd[128];
    __shared__ bool s_is64;
    if (threadIdx.x == 0) s_is64 = targets_are_i64((const int*)targets);
    __syncthreads();

    long long t = get_target(targets, row, s_is64);
    bool valid = (t != IGNORE);
    int safe = valid ? (int)t : 0;

    // float4-vectorized target dot: 1024 elems = 256 float4, 2 per thread
    const float4* er4 = (const float4*)(e + (size_t)row * DIM);
    const float4* cr4 = (const float4*)(c + (size_t)safe * DIM);
    float4 a0 = er4[threadIdx.x],        b0 = cr4[threadIdx.x];
    float4 a1 = er4[threadIdx.x + 128],  b1 = cr4[threadIdx.x + 128];
    float dot = a0.x * b0.x + a0.y * b0.y + a0.z * b0.z + a0.w * b0.w
              + a1.x * b1.x + a1.y * b1.y + a1.z * b1.z + a1.w * b1.w;
    sd[threadIdx.x] = dot;
    __syncthreads();
    for (int off = 64; off > 0; off >>= 1) {
        if (threadIdx.x < off) sd[threadIdx.x] += sd[threadIdx.x + off];
        __syncthreads();
    }

    // warp 0: parallel merge of 148 slice partials
    if (threadIdx.x < 32) {
        const int lane = threadIdx.x;
        float M = NEG_INF, S = 0.0f;
        for (int p = lane; p < NPART; p += 32) {
            float mj = g_pm[p * N_TOK + row];
            float sj = g_ps[p * N_TOK + row];
            if (mj > NEG_INF) {
                if (mj > M) { S = S * __expf(M - mj) + sj; M = mj; }
                else        { S += sj * __expf(mj - M); }
            }
        }
#pragma unroll
        for (int off = 16; off > 0; off >>= 1) {
            float om = __shfl_xor_sync(0xffffffffu, M, off);
            float os = __shfl_xor_sync(0xffffffffu, S, off);
            float nm = fmaxf(M, om);
            float e1 = (M > NEG_INF) ? __expf(M - nm) : 0.0f;
            float e2 = (om > NEG_INF) ? __expf(om - nm) : 0.0f;
            S = S * e1 + os * e2;
            M = nm;
        }
        if (lane == 0) {
            float lse = M + logf(S);
            g_nll[row] = valid ? (lse - sd[0]) : 0.0f;
        }
    }
}

// ---------------------------------------------------------------------------
// Kernel 3: deterministic mean over valid rows
// ---------------------------------------------------------------------------
__global__ __launch_bounds__(1024)
void k_reduce(const void* __restrict__ targets, float* __restrict__ out)
{
    __shared__ float ss[1024];
    __shared__ float sc[1024];
    __shared__ bool  s_is64;
    if (threadIdx.x == 0) s_is64 = targets_are_i64((const int*)targets);
    __syncthreads();

    float sum = 0.0f, cnt = 0.0f;
    for (int r = threadIdx.x; r < N_TOK; r += 1024) {
        sum += g_nll[r];
        long long t = get_target(targets, r, s_is64);
        cnt += (t != IGNORE) ? 1.0f : 0.0f;
    }
    ss[threadIdx.x] = sum;
    sc[threadIdx.x] = cnt;
    __syncthreads();
    for (int off = 512; off > 0; off >>= 1) {
        if (threadIdx.x < off) {
            ss[threadIdx.x] += ss[threadIdx.x + off];
            sc[threadIdx.x] += sc[threadIdx.x + off];
        }
        __syncthreads();
    }
    if (threadIdx.x == 0)
        out[0] = ss[0] / fmaxf(sc[0], 1.0f);
}

// ---------------------------------------------------------------------------
// Host launcher
// ---------------------------------------------------------------------------
extern "C" void kernel_launch(void* const* d_in, const int* in_sizes, int n_in,
                              void* d_out, int out_size)
{
    const float* e = (const float*)d_in[0];
    const float* c = (const float*)d_in[1];
    const void*  t = d_in[2];
    float* out = (float*)d_out;

    void* pe = nullptr; void* pc = nullptr;
    cudaGetSymbolAddress(&pe, g_e16);
    cudaGetSymbolAddress(&pc, g_c16);

    // Pre-round inputs to bf16 (RN)
    {
        int n8e = (N_TOK * DIM) / 8;
        int n8c = (VOCAB * DIM) / 8;
        k_cvt<<<(n8e + 255) / 256, 256>>>((const float4*)e, (uint4*)pe, n8e);
        k_cvt<<<(n8c + 255) / 256, 256>>>((const float4*)c, (uint4*)pc, n8c);
    }

    static int smem_set = 0;
    if (!smem_set) {
        cudaFuncSetAttribute(k_cce, cudaFuncAttributeMaxDynamicSharedMemorySize, SMEM_BYTES);
        smem_set = 1;
    }
    dim3 grid(N_TOK / BM, NSLICES);
    k_cce<<<grid, 256, SMEM_BYTES>>>((const __nv_bfloat16*)pe, (const __nv_bfloat16*)pc);

    k_row_nll<<<N_TOK, 128>>>(e, c, t);
    k_reduce<<<1, 1024>>>(t, out);
}